// round 11
// baseline (speedup 1.0000x reference)
#include <cuda_runtime.h>

// out[b,i,j,c1,c2,k]: k=0 -> x[b,i,c1,c2], k=1 -> x[b,j,c1,c2]
// B=64, GS=96, C=8. CTA = two tiles (b,2m) and (b,2m+1): both share the
// SAME b, hence the SAME 6 xj loads -> per 2 tiles: 2 xi + 6 xj LDG.128
// (instead of 14) and 12 independent STG.256 streaming stores in flight.
// Steady-state we're at the DRAM-write ceiling (~6.4 TB/s); this strips
// the residual read/issue overhead off the write stream.

static constexpr int GS = 96;
static constexpr int ROW = 64;  // 8*8 floats per (b,g) block

__global__ void __launch_bounds__(256)
combo_kernel(const float* __restrict__ x, float* __restrict__ out)
{
    const int pair = blockIdx.x;          // b*48 + m  (i = 2m, 2m+1)
    const int b = pair / (GS / 2);
    const int i0 = (pair % (GS / 2)) * 2;
    const int bi0 = b * GS + i0;

    const int t = threadIdx.x;
    const int lane16 = t & 15;
    const int jbase  = t >> 4;
    const int lane_off = lane16 * 4;

    // xi for both tiles (consecutive rows of x[b])
    const float4 a0 = *reinterpret_cast<const float4*>(x + bi0 * ROW + lane_off);
    const float4 a1 = *reinterpret_cast<const float4*>(x + (bi0 + 1) * ROW + lane_off);

    const float* xb = x + b * GS * ROW + lane_off;
    float* outb0 = out + (size_t)bi0 * GS * 128 + lane16 * 8;
    float* outb1 = outb0 + (size_t)GS * 128;

    // Shared xj loads (MLP=6), feed BOTH tiles
    float4 c[6];
#pragma unroll
    for (int it = 0; it < 6; ++it) {
        const int j = jbase + it * 16;
        c[it] = *reinterpret_cast<const float4*>(xb + j * ROW);
    }

#pragma unroll
    for (int it = 0; it < 6; ++it) {
        const int j = jbase + it * 16;
        float* p0 = outb0 + j * 128;
        asm volatile(
            "st.global.cs.v8.f32 [%0], {%1,%2,%3,%4,%5,%6,%7,%8};" ::
            "l"(p0),
            "f"(a0.x), "f"(c[it].x), "f"(a0.y), "f"(c[it].y),
            "f"(a0.z), "f"(c[it].z), "f"(a0.w), "f"(c[it].w)
            : "memory");
        float* p1 = outb1 + j * 128;
        asm volatile(
            "st.global.cs.v8.f32 [%0], {%1,%2,%3,%4,%5,%6,%7,%8};" ::
            "l"(p1),
            "f"(a1.x), "f"(c[it].x), "f"(a1.y), "f"(c[it].y),
            "f"(a1.z), "f"(c[it].z), "f"(a1.w), "f"(c[it].w)
            : "memory");
    }
}

extern "C" void kernel_launch(void* const* d_in, const int* in_sizes, int n_in,
                              void* d_out, int out_size)
{
    const float* x = (const float*)d_in[0];
    float* out = (float*)d_out;

    // one CTA per (b, i-pair): 64 * 48 = 3072 blocks
    combo_kernel<<<64 * (GS / 2), 256>>>(x, out);
}